// round 11
// baseline (speedup 1.0000x reference)
#include <cuda_runtime.h>
#include <cuda_bf16.h>
#include <cuda_fp16.h>
#include <cstdint>

#define N_NODES 100000
#define N_EDGES 1600000
#define IN_DIM 128
#define HID_DIM 64
#define OUT_DIM 128

#define SCAN_NB 98  // ceil(100000/1024)
#define SCAN_FLAG (1 << 30)
#define APAD 72     // smem row pitch in halves (conflict-free phase-2 reads)

// ---------------------------------------------------------------------------
// Device scratch (no allocations allowed)
// ---------------------------------------------------------------------------
__device__ __half g_h16[N_NODES * HID_DIM];  // h = x@Wc (UNSCALED), fp16
__device__ float  g_dinv[N_NODES];
__device__ int    g_cnt[N_NODES];            // in-degree (no self-loop)
__device__ int    g_off[N_NODES];            // CSR row start
__device__ int    g_slot[N_EDGES];           // per-edge slot within dst row
__device__ int    g_bsum[SCAN_NB];           // lookback aggregates (flag bit 30)
__device__ int    g_srcbin[N_EDGES];         // CSR: src per in-edge, by dst

// Prepacked B fragments for mma.sync m16n8k16 (fp16 hi/lo for both GEMMs).
__device__ uint2 g_WcB_hi[8 * 8 * 32];
__device__ uint2 g_WcB_lo[8 * 8 * 32];
__device__ uint2 g_WlB_hi[4 * 16 * 32];
__device__ uint2 g_WlB_lo[4 * 16 * 32];

// ---------------------------------------------------------------------------
// Helpers
// ---------------------------------------------------------------------------
__device__ __forceinline__ void split2h(float a, float b, uint32_t& hi, uint32_t& lo) {
    __half ha = __float2half_rn(a);
    __half hb = __float2half_rn(b);
    __half la = __float2half_rn(a - __half2float(ha));
    __half lb = __float2half_rn(b - __half2float(hb));
    __half2 hpack = __halves2half2(ha, hb);
    __half2 lpack = __halves2half2(la, lb);
    hi = *reinterpret_cast<uint32_t*>(&hpack);
    lo = *reinterpret_cast<uint32_t*>(&lpack);
}

__device__ __forceinline__ void mma_f16(float* c, uint32_t a0, uint32_t a1,
                                        uint32_t a2, uint32_t a3,
                                        uint32_t b0, uint32_t b1) {
    asm volatile(
        "mma.sync.aligned.m16n8k16.row.col.f32.f16.f16.f32 "
        "{%0,%1,%2,%3}, {%4,%5,%6,%7}, {%8,%9}, {%0,%1,%2,%3};"
        : "+f"(c[0]), "+f"(c[1]), "+f"(c[2]), "+f"(c[3])
        : "r"(a0), "r"(a1), "r"(a2), "r"(a3), "r"(b0), "r"(b1));
}

// ---------------------------------------------------------------------------
// Zero counters / lookback state (stream0 head)
// ---------------------------------------------------------------------------
__global__ void k_zero() {
    int t = blockIdx.x * blockDim.x + threadIdx.x;
    if (t < N_NODES) g_cnt[t] = 0;
    if (t < SCAN_NB) g_bsum[t] = 0;
}

// Weight fragment packing (streamB; independent of everything else)
__global__ void k_initw(const float* __restrict__ Wc, const float* __restrict__ Wl) {
    int t = blockIdx.x * blockDim.x + threadIdx.x;
    if (t < 2048) {  // Wc: 8 kt x 8 nt x 32 lanes
        int lane = t & 31, nt = (t >> 5) & 7, kt = t >> 8;
        int k0 = kt * 16 + (lane & 3) * 2;
        int n = nt * 8 + (lane >> 2);
        uint2 hi, lo;
        split2h(Wc[k0 * HID_DIM + n], Wc[(k0 + 1) * HID_DIM + n], hi.x, lo.x);
        split2h(Wc[(k0 + 8) * HID_DIM + n], Wc[(k0 + 9) * HID_DIM + n], hi.y, lo.y);
        g_WcB_hi[t] = hi;
        g_WcB_lo[t] = lo;
    } else if (t < 4096) {  // Wl: 4 kt x 16 nt x 32 lanes
        int u = t - 2048;
        int lane = u & 31, nt = (u >> 5) & 15, kt = u >> 9;
        int k0 = kt * 16 + (lane & 3) * 2;
        int n = nt * 8 + (lane >> 2);
        uint2 hi, lo;
        split2h(Wl[k0 * OUT_DIM + n], Wl[(k0 + 1) * OUT_DIM + n], hi.x, lo.x);
        split2h(Wl[(k0 + 8) * OUT_DIM + n], Wl[(k0 + 9) * OUT_DIM + n], hi.y, lo.y);
        g_WlB_hi[u] = hi;
        g_WlB_lo[u] = lo;
    }
}

// Count in-degrees AND record each edge's slot within its dst row.
__global__ void k_count(const int* __restrict__ dst) {
    int e4 = blockIdx.x * blockDim.x + threadIdx.x;
    if (e4 >= N_EDGES / 4) return;
    int4 d = ((const int4*)dst)[e4];
    int4 s;
    s.x = atomicAdd(&g_cnt[d.x], 1);
    s.y = atomicAdd(&g_cnt[d.y], 1);
    s.z = atomicAdd(&g_cnt[d.z], 1);
    s.w = atomicAdd(&g_cnt[d.w], 1);
    ((int4*)g_slot)[e4] = s;
}

// ---------------------------------------------------------------------------
// Fused exclusive scan (decoupled lookback) + dinv.
// ---------------------------------------------------------------------------
__global__ __launch_bounds__(256) void k_scan_fused() {
    __shared__ int sh[256];
    int t = threadIdx.x, b = blockIdx.x;
    int base = b * 1024 + t * 4;
    int v[4];
    #pragma unroll
    for (int i = 0; i < 4; i++)
        v[i] = (base + i < N_NODES) ? g_cnt[base + i] : 0;
    int s = v[0] + v[1] + v[2] + v[3];
    sh[t] = s;
    __syncthreads();
    #pragma unroll
    for (int off = 1; off < 256; off <<= 1) {
        int add = (t >= off) ? sh[t - off] : 0;
        __syncthreads();
        sh[t] += add;
        __syncthreads();
    }
    if (t == 255) atomicExch(&g_bsum[b], sh[255] | SCAN_FLAG);
    int ex = sh[t] - s;  // exclusive prefix within block

    int part = 0;
    if (t < b) {
        int val;
        do { val = atomicAdd(&g_bsum[t], 0); } while (!(val & SCAN_FLAG));
        part = val & ~SCAN_FLAG;
    }
    __syncthreads();
    sh[t] = part;
    __syncthreads();
    #pragma unroll
    for (int off = 128; off >= 1; off >>= 1) {
        if (t < off) sh[t] += sh[t + off];
        __syncthreads();
    }
    int boff = sh[0];

    int run = ex + boff;
    #pragma unroll
    for (int i = 0; i < 4; i++) {
        int idx = base + i;
        if (idx < N_NODES) {
            g_off[idx] = run;
            g_dinv[idx] = rsqrtf((float)(v[i] + 1));
            run += v[i];
        }
    }
}

// Bin edges by dst — atomic-free: pos = off[dst] + slot.
__global__ void k_bin(const int* __restrict__ ei) {
    int e4 = blockIdx.x * blockDim.x + threadIdx.x;
    if (e4 >= N_EDGES / 4) return;
    int4 s = ((const int4*)ei)[e4];
    int4 d = ((const int4*)(ei + N_EDGES))[e4];
    int4 sl = ((const int4*)g_slot)[e4];
    g_srcbin[__ldg(&g_off[d.x]) + sl.x] = s.x;
    g_srcbin[__ldg(&g_off[d.y]) + sl.y] = s.y;
    g_srcbin[__ldg(&g_off[d.z]) + sl.z] = s.z;
    g_srcbin[__ldg(&g_off[d.w]) + sl.w] = s.w;
}

// ---------------------------------------------------------------------------
// GEMM1 (HMMA fp16 3-product): g_h16 = fp16(x @ Wc)   [UNSCALED]
// No dependency on the CSR chain -> runs fully parallel on streamB.
// ---------------------------------------------------------------------------
__global__ __launch_bounds__(256) void k_gemm1_mma(const float* __restrict__ x) {
    int tid = threadIdx.x, wid = tid >> 5, lane = tid & 31;
    int rowbase = blockIdx.x * 128 + wid * 16;
    int r0 = rowbase + (lane >> 2);
    int r1 = r0 + 8;
    int kc = (lane & 3) * 2;
    bool v0 = r0 < N_NODES, v1 = r1 < N_NODES;

    float acc[8][4];
    #pragma unroll
    for (int nt = 0; nt < 8; nt++)
        #pragma unroll
        for (int i = 0; i < 4; i++) acc[nt][i] = 0.0f;

    const float2 z2 = make_float2(0.f, 0.f);
    #pragma unroll
    for (int kt = 0; kt < 8; kt++) {
        int k0 = kt * 16 + kc;
        float2 x00 = v0 ? *(const float2*)&x[(size_t)r0 * IN_DIM + k0] : z2;
        float2 x02 = v0 ? *(const float2*)&x[(size_t)r0 * IN_DIM + k0 + 8] : z2;
        float2 x10 = v1 ? *(const float2*)&x[(size_t)r1 * IN_DIM + k0] : z2;
        float2 x12 = v1 ? *(const float2*)&x[(size_t)r1 * IN_DIM + k0 + 8] : z2;
        uint32_t ah0, al0, ah1, al1, ah2, al2, ah3, al3;
        split2h(x00.x, x00.y, ah0, al0);
        split2h(x10.x, x10.y, ah1, al1);
        split2h(x02.x, x02.y, ah2, al2);
        split2h(x12.x, x12.y, ah3, al3);
        const uint2* Bh = &g_WcB_hi[kt * 256 + lane];
        const uint2* Bl = &g_WcB_lo[kt * 256 + lane];
        #pragma unroll
        for (int nt = 0; nt < 8; nt++) {
            uint2 bh = Bh[nt * 32];
            uint2 bl = Bl[nt * 32];
            mma_f16(acc[nt], ah0, ah1, ah2, ah3, bh.x, bh.y);
            mma_f16(acc[nt], ah0, ah1, ah2, ah3, bl.x, bl.y);
            mma_f16(acc[nt], al0, al1, al2, al3, bh.x, bh.y);
        }
    }

    if (v0) {
        #pragma unroll
        for (int nt = 0; nt < 8; nt++) {
            int c = nt * 8 + kc;
            __half2 hv = __floats2half2_rn(acc[nt][0], acc[nt][1]);
            *(__half2*)&g_h16[(size_t)r0 * HID_DIM + c] = hv;
        }
    }
    if (v1) {
        #pragma unroll
        for (int nt = 0; nt < 8; nt++) {
            int c = nt * 8 + kc;
            __half2 hv = __floats2half2_rn(acc[nt][2], acc[nt][3]);
            *(__half2*)&g_h16[(size_t)r1 * HID_DIM + c] = hv;
        }
    }
}

// ---------------------------------------------------------------------------
// FUSED aggregate + GEMM2.
// Phase 1: 128 nodes/block, 2 threads/node x 32 cols.
//   a[n] = relu((h[n]*dinv[n] + sum_src h[src]*dinv[src]) * dinv[n] + bc)
//   -> fp16 into padded smem tile (APAD=72 halves/row).
// Phase 2: out = a @ Wl + bl via m16n8k16 HMMA, A-fragments from smem.
// ---------------------------------------------------------------------------
__global__ __launch_bounds__(256) void k_agg_gemm2(const float* __restrict__ bc,
                                                   const float* __restrict__ bl,
                                                   float* __restrict__ out) {
    __shared__ __half sA[128 * APAD];  // 18432 B
    int tid = threadIdx.x;
    int node0 = blockIdx.x * 128;

    // -------- Phase 1: aggregate --------
    {
        int lrow = tid >> 1;
        int node = node0 + lrow;
        int sub = tid & 1;
        int cbase = sub * 32;

        if (node < N_NODES) {
            float dvn = g_dinv[node];
            float acc[32];
            // self-loop term: h[n] * dinv[n]
            {
                const uint4* hp = (const uint4*)&g_h16[(size_t)node * HID_DIM + cbase];
                #pragma unroll
                for (int q = 0; q < 4; q++) {
                    uint4 hv = hp[q];
                    const __half2* h2 = (const __half2*)&hv;
                    #pragma unroll
                    for (int r = 0; r < 4; r++) {
                        float2 f = __half22float2(h2[r]);
                        acc[q * 8 + r * 2]     = f.x * dvn;
                        acc[q * 8 + r * 2 + 1] = f.y * dvn;
                    }
                }
            }
            int beg = g_off[node];
            int end = beg + g_cnt[node];
            int p = beg;
            // pairs of edges for MLP
            for (; p + 1 < end; p += 2) {
                int s0 = g_srcbin[p];
                int s1 = g_srcbin[p + 1];
                float dv0 = g_dinv[s0];
                float dv1 = g_dinv[s1];
                const uint4* p0 = (const uint4*)&g_h16[(size_t)s0 * HID_DIM + cbase];
                const uint4* p1 = (const uint4*)&g_h16[(size_t)s1 * HID_DIM + cbase];
                uint4 v0[4], v1[4];
                #pragma unroll
                for (int q = 0; q < 4; q++) { v0[q] = p0[q]; v1[q] = p1[q]; }
                #pragma unroll
                for (int q = 0; q < 4; q++) {
                    const __half2* a2 = (const __half2*)&v0[q];
                    const __half2* b2 = (const __half2*)&v1[q];
                    #pragma unroll
                    for (int r = 0; r < 4; r++) {
                        float2 fa = __half22float2(a2[r]);
                        float2 fb = __half22float2(b2[r]);
                        acc[q * 8 + r * 2]     += fa.x * dv0 + fb.x * dv1;
                        acc[q * 8 + r * 2 + 1] += fa.y * dv0 + fb.y * dv1;
                    }
                }
            }
            if (p < end) {
                int s0 = g_srcbin[p];
                float dv0 = g_dinv[s0];
                const uint4* p0 = (const uint4*)&g_h16[(size_t)s0 * HID_DIM + cbase];
                #pragma unroll
                for (int q = 0; q < 4; q++) {
                    uint4 hv = p0[q];
                    const __half2* a2 = (const __half2*)&hv;
                    #pragma unroll
                    for (int r = 0; r < 4; r++) {
                        float2 fa = __half22float2(a2[r]);
                        acc[q * 8 + r * 2]     += fa.x * dv0;
                        acc[q * 8 + r * 2 + 1] += fa.y * dv0;
                    }
                }
            }
            // scale + bias + relu -> smem fp16
            const float4* bp = (const float4*)&bc[cbase];
            #pragma unroll
            for (int q = 0; q < 8; q++) {
                float4 b = bp[q];
                float r0v = fmaxf(acc[q * 4 + 0] * dvn + b.x, 0.f);
                float r1v = fmaxf(acc[q * 4 + 1] * dvn + b.y, 0.f);
                float r2v = fmaxf(acc[q * 4 + 2] * dvn + b.z, 0.f);
                float r3v = fmaxf(acc[q * 4 + 3] * dvn + b.w, 0.f);
                __half2 h0 = __floats2half2_rn(r0v, r1v);
                __half2 h1 = __floats2half2_rn(r2v, r3v);
                *(__half2*)&sA[lrow * APAD + cbase + q * 4]     = h0;
                *(__half2*)&sA[lrow * APAD + cbase + q * 4 + 2] = h1;
            }
        } else {
            __half2 z = __floats2half2_rn(0.f, 0.f);
            #pragma unroll
            for (int c = 0; c < 32; c += 2)
                *(__half2*)&sA[lrow * APAD + cbase + c] = z;
        }
    }
    __syncthreads();

    // -------- Phase 2: GEMM2 from smem --------
    int wid = tid >> 5, lane = tid & 31;
    int lr0 = wid * 16 + (lane >> 2);
    int lr1 = lr0 + 8;
    int r0 = node0 + lr0, r1 = node0 + lr1;
    int kc = (lane & 3) * 2;
    bool v0 = r0 < N_NODES, v1 = r1 < N_NODES;

    float acc2[16][4];
    #pragma unroll
    for (int nt = 0; nt < 16; nt++)
        #pragma unroll
        for (int i = 0; i < 4; i++) acc2[nt][i] = 0.0f;

    #pragma unroll
    for (int kt = 0; kt < 4; kt++) {
        int k0 = kt * 16 + kc;
        uint32_t a0 = *(const uint32_t*)&sA[lr0 * APAD + k0];
        uint32_t a1 = *(const uint32_t*)&sA[lr1 * APAD + k0];
        uint32_t a2 = *(const uint32_t*)&sA[lr0 * APAD + k0 + 8];
        uint32_t a3 = *(const uint32_t*)&sA[lr1 * APAD + k0 + 8];
        const uint2* Bh = &g_WlB_hi[kt * 512 + lane];
        const uint2* Bl = &g_WlB_lo[kt * 512 + lane];
        #pragma unroll
        for (int nt = 0; nt < 16; nt++) {
            uint2 bh = Bh[nt * 32];
            uint2 blf = Bl[nt * 32];
            mma_f16(acc2[nt], a0, a1, a2, a3, bh.x, bh.y);
            mma_f16(acc2[nt], a0, a1, a2, a3, blf.x, blf.y);
        }
    }

    if (v0) {
        #pragma unroll
        for (int nt = 0; nt < 16; nt++) {
            int c = nt * 8 + kc;
            float2 b = *(const float2*)&bl[c];
            *(float2*)&out[(size_t)r0 * OUT_DIM + c] =
                make_float2(acc2[nt][0] + b.x, acc2[nt][1] + b.y);
        }
    }
    if (v1) {
        #pragma unroll
        for (int nt = 0; nt < 16; nt++) {
            int c = nt * 8 + kc;
            float2 b = *(const float2*)&bl[c];
            *(float2*)&out[(size_t)r1 * OUT_DIM + c] =
                make_float2(acc2[nt][2] + b.x, acc2[nt][3] + b.y);
        }
    }
}

// ---------------------------------------------------------------------------
// Launch — two-stream fork/join:
//   sB:      [fork] initw -> gemm1 -> evB          (no CSR dependency!)
//   stream0: zero -> count -> scan -> bin -> [wait evB] fused agg+gemm2
// ---------------------------------------------------------------------------
extern "C" void kernel_launch(void* const* d_in, const int* in_sizes, int n_in,
                              void* d_out, int out_size) {
    const float* x  = (const float*)d_in[0];
    const int*   ei = (const int*)d_in[1];
    const float* Wc = (const float*)d_in[2];
    const float* bc = (const float*)d_in[3];
    const float* Wl = (const float*)d_in[4];
    const float* bl = (const float*)d_in[5];
    float* out = (float*)d_out;

    static cudaStream_t sB = nullptr;
    static cudaEvent_t evFork, evB;
    if (sB == nullptr) {
        cudaStreamCreateWithFlags(&sB, cudaStreamNonBlocking);
        cudaEventCreateWithFlags(&evFork, cudaEventDisableTiming);
        cudaEventCreateWithFlags(&evB, cudaEventDisableTiming);
    }

    int grid = (N_NODES + 127) / 128;  // 782

    // Fork sB off stream 0
    cudaEventRecord(evFork, 0);
    cudaStreamWaitEvent(sB, evFork, 0);

    // sB: weight pack + gemm1 (fully independent of CSR chain)
    k_initw<<<16, 256, 0, sB>>>(Wc, Wl);
    k_gemm1_mma<<<grid, 256, 0, sB>>>(x);
    cudaEventRecord(evB, sB);

    // stream0: CSR chain
    k_zero<<<(N_NODES + 255) / 256, 256>>>();
    k_count<<<(N_EDGES / 4 + 255) / 256, 256>>>(ei + N_EDGES);
    k_scan_fused<<<SCAN_NB, 256>>>();
    k_bin<<<(N_EDGES / 4 + 255) / 256, 256>>>(ei);

    // Join: fused kernel needs bin (stream0) AND gemm1 (sB)
    cudaStreamWaitEvent(0, evB, 0);
    k_agg_gemm2<<<grid, 256>>>(bc, bl, out);
}

// round 12
// speedup vs baseline: 1.1731x; 1.1731x over previous
#include <cuda_runtime.h>
#include <cuda_bf16.h>
#include <cuda_fp16.h>
#include <cstdint>

#define N_NODES 100000
#define N_EDGES 1600000
#define IN_DIM 128
#define HID_DIM 64
#define OUT_DIM 128

#define SCAN_NB 98  // ceil(100000/1024)
#define SCAN_FLAG (1 << 30)

// ---------------------------------------------------------------------------
// Device scratch (no allocations allowed)
// ---------------------------------------------------------------------------
__device__ __half g_h16[N_NODES * HID_DIM];   // h = x@Wc (UNSCALED), fp16
__device__ __half g_agg16[N_NODES * HID_DIM]; // relu(agg*dinv + bc), fp16
__device__ float  g_dinv[N_NODES];
__device__ int    g_cnt[N_NODES];             // in-degree (no self-loop)
__device__ int    g_off[N_NODES];             // CSR row start
__device__ int    g_slot[N_EDGES];            // per-edge slot within dst row
__device__ int    g_bsum[SCAN_NB];            // lookback aggregates (flag bit 30)
__device__ int    g_srcbin[N_EDGES];          // CSR: src per in-edge, by dst

// Prepacked B fragments for mma.sync m16n8k16 (fp16 hi/lo for both GEMMs).
__device__ uint2 g_WcB_hi[8 * 8 * 32];
__device__ uint2 g_WcB_lo[8 * 8 * 32];
__device__ uint2 g_WlB_hi[4 * 16 * 32];
__device__ uint2 g_WlB_lo[4 * 16 * 32];

// ---------------------------------------------------------------------------
// Helpers
// ---------------------------------------------------------------------------
__device__ __forceinline__ void split2h(float a, float b, uint32_t& hi, uint32_t& lo) {
    __half ha = __float2half_rn(a);
    __half hb = __float2half_rn(b);
    __half la = __float2half_rn(a - __half2float(ha));
    __half lb = __float2half_rn(b - __half2float(hb));
    __half2 hpack = __halves2half2(ha, hb);
    __half2 lpack = __halves2half2(la, lb);
    hi = *reinterpret_cast<uint32_t*>(&hpack);
    lo = *reinterpret_cast<uint32_t*>(&lpack);
}

__device__ __forceinline__ void mma_f16(float* c, uint32_t a0, uint32_t a1,
                                        uint32_t a2, uint32_t a3,
                                        uint32_t b0, uint32_t b1) {
    asm volatile(
        "mma.sync.aligned.m16n8k16.row.col.f32.f16.f16.f32 "
        "{%0,%1,%2,%3}, {%4,%5,%6,%7}, {%8,%9}, {%0,%1,%2,%3};"
        : "+f"(c[0]), "+f"(c[1]), "+f"(c[2]), "+f"(c[3])
        : "r"(a0), "r"(a1), "r"(a2), "r"(a3), "r"(b0), "r"(b1));
}

// ---------------------------------------------------------------------------
// Zero counters / lookback state (stream0 head)
// ---------------------------------------------------------------------------
__global__ void k_zero() {
    int t = blockIdx.x * blockDim.x + threadIdx.x;
    if (t < N_NODES) g_cnt[t] = 0;
    if (t < SCAN_NB) g_bsum[t] = 0;
}

// Weight fragment packing (streamB; independent of everything else)
__global__ void k_initw(const float* __restrict__ Wc, const float* __restrict__ Wl) {
    int t = blockIdx.x * blockDim.x + threadIdx.x;
    if (t < 2048) {  // Wc: 8 kt x 8 nt x 32 lanes
        int lane = t & 31, nt = (t >> 5) & 7, kt = t >> 8;
        int k0 = kt * 16 + (lane & 3) * 2;
        int n = nt * 8 + (lane >> 2);
        uint2 hi, lo;
        split2h(Wc[k0 * HID_DIM + n], Wc[(k0 + 1) * HID_DIM + n], hi.x, lo.x);
        split2h(Wc[(k0 + 8) * HID_DIM + n], Wc[(k0 + 9) * HID_DIM + n], hi.y, lo.y);
        g_WcB_hi[t] = hi;
        g_WcB_lo[t] = lo;
    } else if (t < 4096) {  // Wl: 4 kt x 16 nt x 32 lanes
        int u = t - 2048;
        int lane = u & 31, nt = (u >> 5) & 15, kt = u >> 9;
        int k0 = kt * 16 + (lane & 3) * 2;
        int n = nt * 8 + (lane >> 2);
        uint2 hi, lo;
        split2h(Wl[k0 * OUT_DIM + n], Wl[(k0 + 1) * OUT_DIM + n], hi.x, lo.x);
        split2h(Wl[(k0 + 8) * OUT_DIM + n], Wl[(k0 + 9) * OUT_DIM + n], hi.y, lo.y);
        g_WlB_hi[u] = hi;
        g_WlB_lo[u] = lo;
    }
}

// Count in-degrees AND record each edge's slot within its dst row.
__global__ void k_count(const int* __restrict__ dst) {
    int e4 = blockIdx.x * blockDim.x + threadIdx.x;
    if (e4 >= N_EDGES / 4) return;
    int4 d = ((const int4*)dst)[e4];
    int4 s;
    s.x = atomicAdd(&g_cnt[d.x], 1);
    s.y = atomicAdd(&g_cnt[d.y], 1);
    s.z = atomicAdd(&g_cnt[d.z], 1);
    s.w = atomicAdd(&g_cnt[d.w], 1);
    ((int4*)g_slot)[e4] = s;
}

// ---------------------------------------------------------------------------
// Fused exclusive scan (decoupled lookback) + dinv.
// ---------------------------------------------------------------------------
__global__ __launch_bounds__(256) void k_scan_fused() {
    __shared__ int sh[256];
    int t = threadIdx.x, b = blockIdx.x;
    int base = b * 1024 + t * 4;
    int v[4];
    #pragma unroll
    for (int i = 0; i < 4; i++)
        v[i] = (base + i < N_NODES) ? g_cnt[base + i] : 0;
    int s = v[0] + v[1] + v[2] + v[3];
    sh[t] = s;
    __syncthreads();
    #pragma unroll
    for (int off = 1; off < 256; off <<= 1) {
        int add = (t >= off) ? sh[t - off] : 0;
        __syncthreads();
        sh[t] += add;
        __syncthreads();
    }
    if (t == 255) atomicExch(&g_bsum[b], sh[255] | SCAN_FLAG);
    int ex = sh[t] - s;  // exclusive prefix within block

    int part = 0;
    if (t < b) {
        int val;
        do { val = atomicAdd(&g_bsum[t], 0); } while (!(val & SCAN_FLAG));
        part = val & ~SCAN_FLAG;
    }
    __syncthreads();
    sh[t] = part;
    __syncthreads();
    #pragma unroll
    for (int off = 128; off >= 1; off >>= 1) {
        if (t < off) sh[t] += sh[t + off];
        __syncthreads();
    }
    int boff = sh[0];

    int run = ex + boff;
    #pragma unroll
    for (int i = 0; i < 4; i++) {
        int idx = base + i;
        if (idx < N_NODES) {
            g_off[idx] = run;
            g_dinv[idx] = rsqrtf((float)(v[i] + 1));
            run += v[i];
        }
    }
}

// Bin edges by dst — atomic-free: pos = off[dst] + slot.
__global__ void k_bin(const int* __restrict__ ei) {
    int e4 = blockIdx.x * blockDim.x + threadIdx.x;
    if (e4 >= N_EDGES / 4) return;
    int4 s = ((const int4*)ei)[e4];
    int4 d = ((const int4*)(ei + N_EDGES))[e4];
    int4 sl = ((const int4*)g_slot)[e4];
    g_srcbin[__ldg(&g_off[d.x]) + sl.x] = s.x;
    g_srcbin[__ldg(&g_off[d.y]) + sl.y] = s.y;
    g_srcbin[__ldg(&g_off[d.z]) + sl.z] = s.z;
    g_srcbin[__ldg(&g_off[d.w]) + sl.w] = s.w;
}

// ---------------------------------------------------------------------------
// GEMM1 (HMMA fp16 3-product): g_h16 = fp16(x @ Wc)   [UNSCALED]
// No dependency on the CSR chain -> runs fully parallel on streamB.
// ---------------------------------------------------------------------------
__global__ __launch_bounds__(256) void k_gemm1_mma(const float* __restrict__ x) {
    int tid = threadIdx.x, wid = tid >> 5, lane = tid & 31;
    int rowbase = blockIdx.x * 128 + wid * 16;
    int r0 = rowbase + (lane >> 2);
    int r1 = r0 + 8;
    int kc = (lane & 3) * 2;
    bool v0 = r0 < N_NODES, v1 = r1 < N_NODES;

    float acc[8][4];
    #pragma unroll
    for (int nt = 0; nt < 8; nt++)
        #pragma unroll
        for (int i = 0; i < 4; i++) acc[nt][i] = 0.0f;

    const float2 z2 = make_float2(0.f, 0.f);
    #pragma unroll
    for (int kt = 0; kt < 8; kt++) {
        int k0 = kt * 16 + kc;
        float2 x00 = v0 ? *(const float2*)&x[(size_t)r0 * IN_DIM + k0] : z2;
        float2 x02 = v0 ? *(const float2*)&x[(size_t)r0 * IN_DIM + k0 + 8] : z2;
        float2 x10 = v1 ? *(const float2*)&x[(size_t)r1 * IN_DIM + k0] : z2;
        float2 x12 = v1 ? *(const float2*)&x[(size_t)r1 * IN_DIM + k0 + 8] : z2;
        uint32_t ah0, al0, ah1, al1, ah2, al2, ah3, al3;
        split2h(x00.x, x00.y, ah0, al0);
        split2h(x10.x, x10.y, ah1, al1);
        split2h(x02.x, x02.y, ah2, al2);
        split2h(x12.x, x12.y, ah3, al3);
        const uint2* Bh = &g_WcB_hi[kt * 256 + lane];
        const uint2* Bl = &g_WcB_lo[kt * 256 + lane];
        #pragma unroll
        for (int nt = 0; nt < 8; nt++) {
            uint2 bh = Bh[nt * 32];
            uint2 bl = Bl[nt * 32];
            mma_f16(acc[nt], ah0, ah1, ah2, ah3, bh.x, bh.y);
            mma_f16(acc[nt], ah0, ah1, ah2, ah3, bl.x, bl.y);
            mma_f16(acc[nt], al0, al1, al2, al3, bh.x, bh.y);
        }
    }

    if (v0) {
        #pragma unroll
        for (int nt = 0; nt < 8; nt++) {
            int c = nt * 8 + kc;
            __half2 hv = __floats2half2_rn(acc[nt][0], acc[nt][1]);
            *(__half2*)&g_h16[(size_t)r0 * HID_DIM + c] = hv;
        }
    }
    if (v1) {
        #pragma unroll
        for (int nt = 0; nt < 8; nt++) {
            int c = nt * 8 + kc;
            __half2 hv = __floats2half2_rn(acc[nt][2], acc[nt][3]);
            *(__half2*)&g_h16[(size_t)r1 * HID_DIM + c] = hv;
        }
    }
}

// ---------------------------------------------------------------------------
// CSR aggregate (atomic-free, fp16 gather, per-src dinv FMA) + bias/relu:
// agg16[n] = fp16(relu((h[n]*dinv[n] + sum_src h[src]*dinv[src]) * dinv[n] + bc))
// Block 256 = 32 nodes x 8 threads; thread owns 8 of 64 cols.
// ---------------------------------------------------------------------------
__global__ __launch_bounds__(256) void k_aggregate(const float* __restrict__ bc) {
    int tid = threadIdx.x;
    int node = blockIdx.x * 32 + (tid >> 3);
    int sub = tid & 7;
    if (node >= N_NODES) return;
    unsigned gmask = 0xffu << ((tid & 31) & ~7);  // own 8-thread group

    int beg = g_off[node];
    int cnt = g_cnt[node];
    int end = beg + cnt;
    float dvn = g_dinv[node];

    float acc[8];
    {   // self-loop term: h[n] * dinv[n]
        uint4 hv = *(const uint4*)&g_h16[(size_t)node * HID_DIM + sub * 8];
        const __half2* hp = (const __half2*)&hv;
        #pragma unroll
        for (int q = 0; q < 4; q++) {
            float2 f = __half22float2(hp[q]);
            acc[q * 2]     = f.x * dvn;
            acc[q * 2 + 1] = f.y * dvn;
        }
    }

    int p = beg;
    int full_end = beg + (cnt & ~7);
    for (; p < full_end; p += 8) {
        int mysrc = g_srcbin[p + sub];
        float mydv = g_dinv[mysrc];
        #pragma unroll
        for (int j = 0; j < 8; j++) {
            int s = __shfl_sync(gmask, mysrc, j, 8);
            float dv = __shfl_sync(gmask, mydv, j, 8);
            uint4 hv = *(const uint4*)&g_h16[(size_t)s * HID_DIM + sub * 8];
            const __half2* hp = (const __half2*)&hv;
            #pragma unroll
            for (int q = 0; q < 4; q++) {
                float2 f = __half22float2(hp[q]);
                acc[q * 2]     += f.x * dv;
                acc[q * 2 + 1] += f.y * dv;
            }
        }
    }
    if (p < end) {
        int mye = p + sub;
        int mysrc = (mye < end) ? g_srcbin[mye] : 0;
        float mydv = g_dinv[mysrc];
        int m = end - p;
        #pragma unroll
        for (int j = 0; j < 8; j++) {
            if (j < m) {
                int s = __shfl_sync(gmask, mysrc, j, 8);
                float dv = __shfl_sync(gmask, mydv, j, 8);
                uint4 hv = *(const uint4*)&g_h16[(size_t)s * HID_DIM + sub * 8];
                const __half2* hp = (const __half2*)&hv;
                #pragma unroll
                for (int q = 0; q < 4; q++) {
                    float2 f = __half22float2(hp[q]);
                    acc[q * 2]     += f.x * dv;
                    acc[q * 2 + 1] += f.y * dv;
                }
            }
        }
    }

    float4 b0 = *(const float4*)&bc[sub * 8];
    float4 b1 = *(const float4*)&bc[sub * 8 + 4];
    float r[8];
    r[0] = fmaxf(acc[0] * dvn + b0.x, 0.f);
    r[1] = fmaxf(acc[1] * dvn + b0.y, 0.f);
    r[2] = fmaxf(acc[2] * dvn + b0.z, 0.f);
    r[3] = fmaxf(acc[3] * dvn + b0.w, 0.f);
    r[4] = fmaxf(acc[4] * dvn + b1.x, 0.f);
    r[5] = fmaxf(acc[5] * dvn + b1.y, 0.f);
    r[6] = fmaxf(acc[6] * dvn + b1.z, 0.f);
    r[7] = fmaxf(acc[7] * dvn + b1.w, 0.f);
    uint4 ov;
    __half2 p0 = __floats2half2_rn(r[0], r[1]);
    __half2 p1 = __floats2half2_rn(r[2], r[3]);
    __half2 p2 = __floats2half2_rn(r[4], r[5]);
    __half2 p3 = __floats2half2_rn(r[6], r[7]);
    ov.x = *reinterpret_cast<uint32_t*>(&p0);
    ov.y = *reinterpret_cast<uint32_t*>(&p1);
    ov.z = *reinterpret_cast<uint32_t*>(&p2);
    ov.w = *reinterpret_cast<uint32_t*>(&p3);
    *(uint4*)&g_agg16[(size_t)node * HID_DIM + sub * 8] = ov;
}

// ---------------------------------------------------------------------------
// GEMM2 (HMMA f16 2-product): out = agg16 @ Wl + bl
// ---------------------------------------------------------------------------
__global__ __launch_bounds__(256) void k_gemm2_mma(const float* __restrict__ bl,
                                                   float* __restrict__ out) {
    int tid = threadIdx.x, wid = tid >> 5, lane = tid & 31;
    int rowbase = blockIdx.x * 128 + wid * 16;
    int r0 = rowbase + (lane >> 2);
    int r1 = r0 + 8;
    int kc = (lane & 3) * 2;
    bool v0 = r0 < N_NODES, v1 = r1 < N_NODES;

    float acc[16][4];
    #pragma unroll
    for (int nt = 0; nt < 16; nt++)
        #pragma unroll
        for (int i = 0; i < 4; i++) acc[nt][i] = 0.0f;

    #pragma unroll
    for (int kt = 0; kt < 4; kt++) {
        int k0 = kt * 16 + kc;
        uint32_t a0 = 0, a1 = 0, a2 = 0, a3 = 0;
        if (v0) {
            a0 = *(const uint32_t*)&g_agg16[(size_t)r0 * HID_DIM + k0];
            a2 = *(const uint32_t*)&g_agg16[(size_t)r0 * HID_DIM + k0 + 8];
        }
        if (v1) {
            a1 = *(const uint32_t*)&g_agg16[(size_t)r1 * HID_DIM + k0];
            a3 = *(const uint32_t*)&g_agg16[(size_t)r1 * HID_DIM + k0 + 8];
        }
        const uint2* Bh = &g_WlB_hi[kt * 512 + lane];
        const uint2* Bl = &g_WlB_lo[kt * 512 + lane];
        #pragma unroll
        for (int nt = 0; nt < 16; nt++) {
            uint2 bh = Bh[nt * 32];
            uint2 blf = Bl[nt * 32];
            mma_f16(acc[nt], a0, a1, a2, a3, bh.x, bh.y);
            mma_f16(acc[nt], a0, a1, a2, a3, blf.x, blf.y);
        }
    }

    if (v0) {
        #pragma unroll
        for (int nt = 0; nt < 16; nt++) {
            int c = nt * 8 + kc;
            float2 b = *(const float2*)&bl[c];
            *(float2*)&out[(size_t)r0 * OUT_DIM + c] =
                make_float2(acc[nt][0] + b.x, acc[nt][1] + b.y);
        }
    }
    if (v1) {
        #pragma unroll
        for (int nt = 0; nt < 16; nt++) {
            int c = nt * 8 + kc;
            float2 b = *(const float2*)&bl[c];
            *(float2*)&out[(size_t)r1 * OUT_DIM + c] =
                make_float2(acc[nt][2] + b.x, acc[nt][3] + b.y);
        }
    }
}

// ---------------------------------------------------------------------------
// Launch — two-stream fork/join:
//   sB:      [fork] initw -> gemm1 -> evB    (no CSR dependency at all)
//   stream0: zero -> count -> scan -> bin -> [wait evB] aggregate -> gemm2
// ---------------------------------------------------------------------------
extern "C" void kernel_launch(void* const* d_in, const int* in_sizes, int n_in,
                              void* d_out, int out_size) {
    const float* x  = (const float*)d_in[0];
    const int*   ei = (const int*)d_in[1];
    const float* Wc = (const float*)d_in[2];
    const float* bc = (const float*)d_in[3];
    const float* Wl = (const float*)d_in[4];
    const float* bl = (const float*)d_in[5];
    float* out = (float*)d_out;

    static cudaStream_t sB = nullptr;
    static cudaEvent_t evFork, evB;
    if (sB == nullptr) {
        cudaStreamCreateWithFlags(&sB, cudaStreamNonBlocking);
        cudaEventCreateWithFlags(&evFork, cudaEventDisableTiming);
        cudaEventCreateWithFlags(&evB, cudaEventDisableTiming);
    }

    int grid = (N_NODES + 127) / 128;  // 782

    // Fork sB off stream 0
    cudaEventRecord(evFork, 0);
    cudaStreamWaitEvent(sB, evFork, 0);

    // sB: weight pack + gemm1 (fully independent of CSR chain)
    k_initw<<<16, 256, 0, sB>>>(Wc, Wl);
    k_gemm1_mma<<<grid, 256, 0, sB>>>(x);
    cudaEventRecord(evB, sB);

    // stream0: CSR chain
    k_zero<<<(N_NODES + 255) / 256, 256>>>();
    k_count<<<(N_EDGES / 4 + 255) / 256, 256>>>(ei + N_EDGES);
    k_scan_fused<<<SCAN_NB, 256>>>();
    k_bin<<<(N_EDGES / 4 + 255) / 256, 256>>>(ei);

    // Join: aggregate needs bin (stream0) AND gemm1 (sB)
    cudaStreamWaitEvent(0, evB, 0);
    k_aggregate<<<(N_NODES + 31) / 32, 256>>>(bc);
    k_gemm2_mma<<<grid, 256>>>(bl, out);
}